// round 3
// baseline (speedup 1.0000x reference)
#include <cuda_runtime.h>

#define DIMX 1024
#define NEXP 8
#define HIDX 4096
#define TTOK 4096   // B*S = 2*2048

// ---------------- static scratch (no allocations allowed) ----------------
__device__ signed char g_wq1[(size_t)NEXP * HIDX * DIMX];   // ternary w1, 33.5MB
__device__ signed char g_wq2[(size_t)NEXP * DIMX * HIDX];   // ternary w2, 33.5MB
__device__ signed char g_wqr[NEXP * DIMX];
__device__ signed char g_wqn[NEXP * DIMX];
__device__ float g_partial[18 * 64];
__device__ float g_mval[18];                                 // dequant scales (mean|w| clipped)
__device__ signed char g_xq[(size_t)TTOK * DIMX];            // int8 activations
__device__ float g_deqx[TTOK];                               // per-token dequant
__device__ int   g_cnt[NEXP];
__device__ int   g_off[NEXP];
__device__ int   g_tok[NEXP * TTOK];
__device__ float g_gate[NEXP * TTOK];
__device__ float g_h[(size_t)2 * TTOK * HIDX];               // fp32 hidden, 134MB
__device__ signed char g_hq[(size_t)2 * TTOK * HIDX];        // int8 hidden
__device__ float g_deqh[2 * TTOK];

// ---------------- helpers ----------------
__device__ __forceinline__ signed char terq(float x) {
    float r = rintf(x);
    r = fminf(1.f, fmaxf(-1.f, r));
    return (signed char)(int)r;
}
__device__ __forceinline__ signed char qi8(float x) {
    float r = rintf(x);
    r = fminf(127.f, fmaxf(-128.f, r));
    return (signed char)(int)r;
}

// ---------------- weight stats: sum |w| per tensor/expert ----------------
__global__ void stats_partial(const float* __restrict__ wr, const float* __restrict__ wn,
                              const float* __restrict__ w1, const float* __restrict__ w2) {
    int slot = blockIdx.y, chunk = blockIdx.x;
    const float4* p;
    int nvec;
    if (slot < 2) {
        if (chunk != 0) return;
        p = (const float4*)(slot ? wn : wr);
        nvec = NEXP * DIMX / 4;
    } else if (slot < 10) {
        p = (const float4*)(w1 + (size_t)(slot - 2) * HIDX * DIMX) + (size_t)chunk * 16384;
        nvec = 16384;
    } else {
        p = (const float4*)(w2 + (size_t)(slot - 10) * DIMX * HIDX) + (size_t)chunk * 16384;
        nvec = 16384;
    }
    float s = 0.f;
    for (int i = threadIdx.x; i < nvec; i += 256) {
        float4 v = p[i];
        s += fabsf(v.x) + fabsf(v.y) + fabsf(v.z) + fabsf(v.w);
    }
    __shared__ float sh[8];
    #pragma unroll
    for (int o = 16; o; o >>= 1) s += __shfl_xor_sync(0xffffffffu, s, o);
    if ((threadIdx.x & 31) == 0) sh[threadIdx.x >> 5] = s;
    __syncthreads();
    if (threadIdx.x == 0) {
        float t = 0.f;
        #pragma unroll
        for (int j = 0; j < 8; j++) t += sh[j];
        g_partial[slot * 64 + chunk] = t;
    }
}

__global__ void stats_final() {
    int s = threadIdx.x;
    if (s >= 18) return;
    int nc = (s < 2) ? 1 : 64;
    float sum = 0.f;
    for (int c = 0; c < nc; c++) sum += g_partial[s * 64 + c];
    float nelem = (s < 2) ? (float)(NEXP * DIMX) : (float)((size_t)HIDX * DIMX);
    g_mval[s] = fmaxf(sum / nelem, 1e-5f);
}

// ---------------- weight ternarization ----------------
__global__ void wquant_small(const float* __restrict__ wr, const float* __restrict__ wn) {
    int i = blockIdx.x * 256 + threadIdx.x;   // 0 .. 16383
    if (i < NEXP * DIMX) {
        float sc = 1.0f / g_mval[0];
        g_wqr[i] = terq(wr[i] * sc);
    } else {
        int j = i - NEXP * DIMX;
        float sc = 1.0f / g_mval[1];
        g_wqn[j] = terq(wn[j] * sc);
    }
}

__global__ void wquant_big(const float* __restrict__ w, int which) {
    size_t i = (size_t)blockIdx.x * 256 + threadIdx.x;   // float4 index
    const size_t nvec = (size_t)NEXP * HIDX * DIMX / 4;  // 8388608
    if (i >= nvec) return;
    int e = (int)(i >> 20);                              // 1048576 float4 per expert
    float sc = 1.0f / g_mval[(which == 1 ? 2 : 10) + e];
    float4 v = ((const float4*)w)[i];
    char4 c;
    c.x = terq(v.x * sc); c.y = terq(v.y * sc); c.z = terq(v.z * sc); c.w = terq(v.w * sc);
    signed char* dst = (which == 1) ? g_wq1 : g_wq2;
    ((char4*)dst)[i] = c;
}

// ---------------- activation quant (rmsnorm + int8 absmax) ----------------
__global__ void act_quant(const float* __restrict__ x) {
    int t = blockIdx.x;
    int tid = threadIdx.x;
    float4 v = ((const float4*)(x + (size_t)t * DIMX))[tid];
    float ss = v.x * v.x + v.y * v.y + v.z * v.z + v.w * v.w;
    float am = fmaxf(fmaxf(fabsf(v.x), fabsf(v.y)), fmaxf(fabsf(v.z), fabsf(v.w)));
    __shared__ float shs[8], shm[8];
    #pragma unroll
    for (int o = 16; o; o >>= 1) {
        ss += __shfl_xor_sync(0xffffffffu, ss, o);
        am = fmaxf(am, __shfl_xor_sync(0xffffffffu, am, o));
    }
    if ((tid & 31) == 0) { shs[tid >> 5] = ss; shm[tid >> 5] = am; }
    __syncthreads();
    float tss = 0.f, tam = 0.f;
    #pragma unroll
    for (int j = 0; j < 8; j++) { tss += shs[j]; tam = fmaxf(tam, shm[j]); }
    float rs = rsqrtf(tss / (float)DIMX + 1e-6f);
    float a = fmaxf(tam * rs, 1e-5f);
    float sc = 127.0f / a;
    if (tid == 0) g_deqx[t] = a / 127.0f;
    char4 c;
    c.x = qi8(v.x * rs * sc); c.y = qi8(v.y * rs * sc);
    c.z = qi8(v.z * rs * sc); c.w = qi8(v.w * rs * sc);
    ((char4*)(g_xq + (size_t)t * DIMX))[tid] = c;
}

// ---------------- router: 16 dp4a dots, noisy top-2, gates, expert lists ----------------
__global__ void router_kernel(const float* __restrict__ eps) {
    int t = blockIdx.x * 8 + (threadIdx.x >> 5);
    int lane = threadIdx.x & 31;
    const int* xp = (const int*)(g_xq + (size_t)t * DIMX);
    int xi[8];
    #pragma unroll
    for (int j = 0; j < 8; j++) xi[j] = xp[lane + 32 * j];
    float dq = g_deqx[t];
    float vals[NEXP];
    #pragma unroll
    for (int e = 0; e < NEXP; e++) {
        const int* wrp = (const int*)(g_wqr + e * DIMX);
        const int* wnp = (const int*)(g_wqn + e * DIMX);
        int ar = 0, an = 0;
        #pragma unroll
        for (int j = 0; j < 8; j++) {
            ar = __dp4a(xi[j], wrp[lane + 32 * j], ar);
            an = __dp4a(xi[j], wnp[lane + 32 * j], an);
        }
        #pragma unroll
        for (int o = 16; o; o >>= 1) {
            ar += __shfl_xor_sync(0xffffffffu, ar, o);
            an += __shfl_xor_sync(0xffffffffu, an, o);
        }
        if (lane == 0) {
            float lg = (float)ar * dq * g_mval[0];
            float nl = (float)an * dq * g_mval[1];
            float sp = fmaxf(nl, 0.f) + log1pf(expf(-fabsf(nl)));   // softplus (stable)
            vals[e] = lg + eps[t * NEXP + e] * sp;
        }
    }
    if (lane == 0) {
        float v0 = -1e30f, v1 = -1e30f;
        int i0 = 0, i1 = 0;
        #pragma unroll
        for (int e = 0; e < NEXP; e++) {
            float v = vals[e];
            if (v > v0) { v1 = v0; i1 = i0; v0 = v; i0 = e; }
            else if (v > v1) { v1 = v; i1 = e; }
        }
        float ex = expf(v1 - v0);
        float inv = 1.0f / (1.0f + ex);
        float g0 = inv, g1 = ex * inv;
        int p0 = atomicAdd(&g_cnt[i0], 1);
        g_tok[i0 * TTOK + p0] = t;
        g_gate[i0 * TTOK + p0] = g0;
        int p1 = atomicAdd(&g_cnt[i1], 1);
        g_tok[i1 * TTOK + p1] = t;
        g_gate[i1 * TTOK + p1] = g1;
    }
}

__global__ void zero_cnt() { if (threadIdx.x < NEXP) g_cnt[threadIdx.x] = 0; }

__global__ void scan_off() {
    if (threadIdx.x == 0) {
        int o = 0;
        for (int e = 0; e < NEXP; e++) { g_off[e] = o; o += g_cnt[e]; }
    }
}

// ---------------- per-row hidden quant (rmsnorm + int8) ----------------
__global__ void h_quant() {
    int e = blockIdx.y, pos = blockIdx.x;
    if (pos >= g_cnt[e]) return;
    size_t row = (size_t)g_off[e] + pos;
    const float4* hp = (const float4*)(g_h + row * HIDX);
    int tid = threadIdx.x;
    float4 r[4];
    float ss = 0.f, am = 0.f;
    #pragma unroll
    for (int j = 0; j < 4; j++) {
        r[j] = hp[tid + 256 * j];
        ss += r[j].x * r[j].x + r[j].y * r[j].y + r[j].z * r[j].z + r[j].w * r[j].w;
        am = fmaxf(am, fmaxf(fmaxf(fabsf(r[j].x), fabsf(r[j].y)), fmaxf(fabsf(r[j].z), fabsf(r[j].w))));
    }
    __shared__ float shs[8], shm[8];
    #pragma unroll
    for (int o = 16; o; o >>= 1) {
        ss += __shfl_xor_sync(0xffffffffu, ss, o);
        am = fmaxf(am, __shfl_xor_sync(0xffffffffu, am, o));
    }
    if ((tid & 31) == 0) { shs[tid >> 5] = ss; shm[tid >> 5] = am; }
    __syncthreads();
    float tss = 0.f, tam = 0.f;
    #pragma unroll
    for (int j = 0; j < 8; j++) { tss += shs[j]; tam = fmaxf(tam, shm[j]); }
    float rs = rsqrtf(tss / (float)HIDX + 1e-6f);
    float a = fmaxf(tam * rs, 1e-5f);
    float sc = 127.0f / a;
    if (tid == 0) g_deqh[row] = a / 127.0f;
    char4* dst = (char4*)(g_hq + row * HIDX);
    #pragma unroll
    for (int j = 0; j < 4; j++) {
        char4 c;
        c.x = qi8(r[j].x * rs * sc); c.y = qi8(r[j].y * rs * sc);
        c.z = qi8(r[j].z * rs * sc); c.w = qi8(r[j].w * rs * sc);
        dst[tid + 256 * j] = c;
    }
}

// ---------------- int8 tensor-core grouped GEMM ----------------
#define BM 128
#define BN 128
#define BKK 64
#define LDSS 80   // 64 + 16 pad: conflict-free fragment reads

__device__ __forceinline__ void mma8(int (&c)[4], const unsigned (&a)[4], const unsigned (&b)[2]) {
    asm volatile(
        "mma.sync.aligned.m16n8k32.row.col.s32.s8.s8.s32 "
        "{%0,%1,%2,%3}, {%4,%5,%6,%7}, {%8,%9}, {%0,%1,%2,%3};\n"
        : "+r"(c[0]), "+r"(c[1]), "+r"(c[2]), "+r"(c[3])
        : "r"(a[0]), "r"(a[1]), "r"(a[2]), "r"(a[3]), "r"(b[0]), "r"(b[1]));
}

template <int MODE>
__global__ __launch_bounds__(256) void bit_gemm(float* __restrict__ out) {
    constexpr int K = (MODE == 1) ? DIMX : HIDX;
    constexpr int N = (MODE == 1) ? HIDX : DIMX;
    const int e = blockIdx.z;
    const int cnt = g_cnt[e];
    const int m0 = blockIdx.y * BM;
    if (m0 >= cnt) return;
    const int n0 = blockIdx.x * BN;
    const int off = g_off[e];

    __shared__ signed char sA[BM * LDSS];
    __shared__ signed char sB[BN * LDSS];

    const int tid = threadIdx.x;
    const int lane = tid & 31, warp = tid >> 5;
    const int wm = warp >> 2, wn = warp & 3;   // 2x4 warp grid

    int acc[4][4][4];
    #pragma unroll
    for (int a = 0; a < 4; a++)
        #pragma unroll
        for (int b = 0; b < 4; b++)
            #pragma unroll
            for (int c = 0; c < 4; c++) acc[a][b][c] = 0;

    const int lr = tid >> 1;
    const int lcb = (tid & 1) * 32;
    const bool aok = (m0 + lr) < cnt;
    const signed char* Ap;
    if (MODE == 1) {
        int tok = aok ? g_tok[e * TTOK + m0 + lr] : 0;
        Ap = g_xq + (size_t)tok * K + lcb;
    } else {
        int r = aok ? (off + m0 + lr) : 0;
        Ap = g_hq + (size_t)r * K + lcb;
    }
    const signed char* wsrc = (MODE == 1) ? g_wq1 : g_wq2;
    const signed char* Bp = wsrc + (size_t)e * N * K + (size_t)(n0 + lr) * K + lcb;

    signed char* sArow = sA + lr * LDSS + lcb;
    signed char* sBrow = sB + lr * LDSS + lcb;

    for (int kb = 0; kb < K; kb += BKK) {
        int4 a0 = make_int4(0, 0, 0, 0), a1 = a0;
        if (aok) {
            a0 = *(const int4*)(Ap + kb);
            a1 = *(const int4*)(Ap + kb + 16);
        }
        int4 b0 = *(const int4*)(Bp + kb);
        int4 b1 = *(const int4*)(Bp + kb + 16);
        __syncthreads();
        *(int4*)(sArow) = a0;
        *(int4*)(sArow + 16) = a1;
        *(int4*)(sBrow) = b0;
        *(int4*)(sBrow + 16) = b1;
        __syncthreads();

        #pragma unroll
        for (int ks = 0; ks < 2; ks++) {
            unsigned af[4][4];
            #pragma unroll
            for (int mi = 0; mi < 4; mi++) {
                const signed char* p = sA + (wm * 64 + mi * 16 + (lane >> 2)) * LDSS + ks * 32 + (lane & 3) * 4;
                af[mi][0] = *(const unsigned*)p;
                af[mi][1] = *(const unsigned*)(p + 8 * LDSS);
                af[mi][2] = *(const unsigned*)(p + 16);
                af[mi][3] = *(const unsigned*)(p + 8 * LDSS + 16);
            }
            unsigned bf[4][2];
            #pragma unroll
            for (int ni = 0; ni < 4; ni++) {
                const signed char* p = sB + (wn * 32 + ni * 8 + (lane >> 2)) * LDSS + ks * 32 + (lane & 3) * 4;
                bf[ni][0] = *(const unsigned*)p;
                bf[ni][1] = *(const unsigned*)(p + 16);
            }
            #pragma unroll
            for (int mi = 0; mi < 4; mi++)
                #pragma unroll
                for (int ni = 0; ni < 4; ni++) mma8(acc[mi][ni], af[mi], bf[ni]);
        }
    }

    if (MODE == 1) {
        const float m1 = g_mval[2 + e];
        #pragma unroll
        for (int mi = 0; mi < 4; mi++) {
            #pragma unroll
            for (int half = 0; half < 2; half++) {
                int rrow = wm * 64 + mi * 16 + (lane >> 2) + half * 8;
                int pos = m0 + rrow;
                if (pos < cnt) {
                    float d = g_deqx[g_tok[e * TTOK + pos]] * m1;
                    float* hrow = g_h + (size_t)(off + pos) * HIDX + n0;
                    #pragma unroll
                    for (int ni = 0; ni < 4; ni++) {
                        int col = wn * 32 + ni * 8 + (lane & 3) * 2;
                        float2 v;
                        v.x = fmaxf(0.f, (float)acc[mi][ni][half * 2 + 0] * d);
                        v.y = fmaxf(0.f, (float)acc[mi][ni][half * 2 + 1] * d);
                        *(float2*)(hrow + col) = v;
                    }
                }
            }
        }
    } else {
        const float m2 = g_mval[10 + e];
        #pragma unroll
        for (int mi = 0; mi < 4; mi++) {
            #pragma unroll
            for (int half = 0; half < 2; half++) {
                int rrow = wm * 64 + mi * 16 + (lane >> 2) + half * 8;
                int pos = m0 + rrow;
                if (pos < cnt) {
                    int tok = g_tok[e * TTOK + pos];
                    float d = g_deqh[off + pos] * m2 * g_gate[e * TTOK + pos];
                    float* orow = out + (size_t)tok * DIMX + n0;
                    #pragma unroll
                    for (int ni = 0; ni < 4; ni++) {
                        int col = wn * 32 + ni * 8 + (lane & 3) * 2;
                        atomicAdd(orow + col, (float)acc[mi][ni][half * 2 + 0] * d);
                        atomicAdd(orow + col + 1, (float)acc[mi][ni][half * 2 + 1] * d);
                    }
                }
            }
        }
    }
}

// ---------------- launch ----------------
extern "C" void kernel_launch(void* const* d_in, const int* in_sizes, int n_in,
                              void* d_out, int out_size) {
    const float* x   = (const float*)d_in[0];
    const float* eps = (const float*)d_in[1];
    const float* wr  = (const float*)d_in[2];
    const float* wn  = (const float*)d_in[3];
    const float* w1  = (const float*)d_in[4];
    const float* w2  = (const float*)d_in[5];
    float* out = (float*)d_out;

    cudaMemsetAsync(d_out, 0, (size_t)out_size * sizeof(float));
    zero_cnt<<<1, 32>>>();
    stats_partial<<<dim3(64, 18), 256>>>(wr, wn, w1, w2);
    stats_final<<<1, 32>>>();
    wquant_small<<<64, 256>>>(wr, wn);
    wquant_big<<<32768, 256>>>(w1, 1);
    wquant_big<<<32768, 256>>>(w2, 2);
    act_quant<<<TTOK, 256>>>(x);
    router_kernel<<<TTOK / 8, 256>>>(eps);
    scan_off<<<1, 32>>>();
    bit_gemm<1><<<dim3(HIDX / BN, TTOK / BM, NEXP), 256>>>(nullptr);
    h_quant<<<dim3(TTOK, NEXP), 256>>>();
    bit_gemm<2><<<dim3(DIMX / BN, TTOK / BM, NEXP), 256>>>(out);
}

// round 6
// speedup vs baseline: 1.1363x; 1.1363x over previous
#include <cuda_runtime.h>
#include <cstdint>

#define DIMX 1024
#define NEXP 8
#define HIDX 4096
#define TTOK 4096   // B*S = 2*2048

// ---------------- static scratch (no allocations allowed) ----------------
__device__ signed char g_wq1[(size_t)NEXP * HIDX * DIMX];   // ternary w1, 33.5MB
__device__ signed char g_wq2[(size_t)NEXP * DIMX * HIDX];   // ternary w2, 33.5MB
__device__ signed char g_wqr[NEXP * DIMX];
__device__ signed char g_wqn[NEXP * DIMX];
__device__ float g_partial[18 * 64];
__device__ float g_mval[18];
__device__ signed char g_xq[(size_t)TTOK * DIMX];
__device__ float g_deqx[TTOK];
__device__ int   g_cnt[NEXP];
__device__ int   g_off[NEXP];
__device__ int   g_tok[NEXP * TTOK];
__device__ int   g_tpe[TTOK * 2];    // (expert<<16)|pos for each token's two slots
__device__ float g_tg[TTOK * 2];     // gates for each token's two slots
__device__ float g_h[(size_t)2 * TTOK * HIDX];               // fp32 hidden
__device__ signed char g_hq[(size_t)2 * TTOK * HIDX];        // int8 hidden
__device__ float g_deqh[2 * TTOK];
__device__ float g_y[(size_t)2 * TTOK * DIMX];               // ungated expert outputs

// ---------------- helpers ----------------
__device__ __forceinline__ signed char terq(float x) {
    float r = rintf(x);
    r = fminf(1.f, fmaxf(-1.f, r));
    return (signed char)(int)r;
}
__device__ __forceinline__ signed char qi8(float x) {
    float r = rintf(x);
    r = fminf(127.f, fmaxf(-128.f, r));
    return (signed char)(int)r;
}
__device__ __forceinline__ uint32_t s2u(const void* p) {
    uint32_t a;
    asm("{ .reg .u64 t; cvta.to.shared.u64 t, %1; cvt.u32.u64 %0, t; }" : "=r"(a) : "l"(p));
    return a;
}

// ---------------- weight stats ----------------
__global__ void stats_partial(const float* __restrict__ wr, const float* __restrict__ wn,
                              const float* __restrict__ w1, const float* __restrict__ w2) {
    int slot = blockIdx.y, chunk = blockIdx.x;
    const float4* p;
    int nvec;
    if (slot < 2) {
        if (chunk != 0) return;
        p = (const float4*)(slot ? wn : wr);
        nvec = NEXP * DIMX / 4;
    } else if (slot < 10) {
        p = (const float4*)(w1 + (size_t)(slot - 2) * HIDX * DIMX) + (size_t)chunk * 16384;
        nvec = 16384;
    } else {
        p = (const float4*)(w2 + (size_t)(slot - 10) * DIMX * HIDX) + (size_t)chunk * 16384;
        nvec = 16384;
    }
    float s = 0.f;
    for (int i = threadIdx.x; i < nvec; i += 256) {
        float4 v = p[i];
        s += fabsf(v.x) + fabsf(v.y) + fabsf(v.z) + fabsf(v.w);
    }
    __shared__ float sh[8];
    #pragma unroll
    for (int o = 16; o; o >>= 1) s += __shfl_xor_sync(0xffffffffu, s, o);
    if ((threadIdx.x & 31) == 0) sh[threadIdx.x >> 5] = s;
    __syncthreads();
    if (threadIdx.x == 0) {
        float t = 0.f;
        #pragma unroll
        for (int j = 0; j < 8; j++) t += sh[j];
        g_partial[slot * 64 + chunk] = t;
    }
}

__global__ void stats_final() {
    int s = threadIdx.x;
    if (s >= 18) return;
    int nc = (s < 2) ? 1 : 64;
    float sum = 0.f;
    for (int c = 0; c < nc; c++) sum += g_partial[s * 64 + c];
    float nelem = (s < 2) ? (float)(NEXP * DIMX) : (float)((size_t)HIDX * DIMX);
    g_mval[s] = fmaxf(sum / nelem, 1e-5f);
}

// ---------------- weight ternarization ----------------
__global__ void wquant_small(const float* __restrict__ wr, const float* __restrict__ wn) {
    int i = blockIdx.x * 256 + threadIdx.x;
    if (i < NEXP * DIMX) {
        float sc = 1.0f / g_mval[0];
        g_wqr[i] = terq(wr[i] * sc);
    } else {
        int j = i - NEXP * DIMX;
        float sc = 1.0f / g_mval[1];
        g_wqn[j] = terq(wn[j] * sc);
    }
}

__global__ void wquant_big(const float* __restrict__ w, int which) {
    size_t i = (size_t)blockIdx.x * 256 + threadIdx.x;   // float4 index
    const size_t nvec = (size_t)NEXP * HIDX * DIMX / 4;
    if (i >= nvec) return;
    int e = (int)(i >> 20);
    float sc = 1.0f / g_mval[(which == 1 ? 2 : 10) + e];
    float4 v = ((const float4*)w)[i];
    char4 c;
    c.x = terq(v.x * sc); c.y = terq(v.y * sc); c.z = terq(v.z * sc); c.w = terq(v.w * sc);
    signed char* dst = (which == 1) ? g_wq1 : g_wq2;
    ((char4*)dst)[i] = c;
}

// ---------------- activation quant ----------------
__global__ void act_quant(const float* __restrict__ x) {
    int t = blockIdx.x;
    int tid = threadIdx.x;
    float4 v = ((const float4*)(x + (size_t)t * DIMX))[tid];
    float ss = v.x * v.x + v.y * v.y + v.z * v.z + v.w * v.w;
    float am = fmaxf(fmaxf(fabsf(v.x), fabsf(v.y)), fmaxf(fabsf(v.z), fabsf(v.w)));
    __shared__ float shs[8], shm[8];
    #pragma unroll
    for (int o = 16; o; o >>= 1) {
        ss += __shfl_xor_sync(0xffffffffu, ss, o);
        am = fmaxf(am, __shfl_xor_sync(0xffffffffu, am, o));
    }
    if ((tid & 31) == 0) { shs[tid >> 5] = ss; shm[tid >> 5] = am; }
    __syncthreads();
    float tss = 0.f, tam = 0.f;
    #pragma unroll
    for (int j = 0; j < 8; j++) { tss += shs[j]; tam = fmaxf(tam, shm[j]); }
    float rs = rsqrtf(tss / (float)DIMX + 1e-6f);
    float a = fmaxf(tam * rs, 1e-5f);
    float sc = 127.0f / a;
    if (tid == 0) g_deqx[t] = a / 127.0f;
    char4 c;
    c.x = qi8(v.x * rs * sc); c.y = qi8(v.y * rs * sc);
    c.z = qi8(v.z * rs * sc); c.w = qi8(v.w * rs * sc);
    ((char4*)(g_xq + (size_t)t * DIMX))[tid] = c;
}

// ---------------- router ----------------
__global__ void router_kernel(const float* __restrict__ eps) {
    int t = blockIdx.x * 8 + (threadIdx.x >> 5);
    int lane = threadIdx.x & 31;
    const int* xp = (const int*)(g_xq + (size_t)t * DIMX);
    int xi[8];
    #pragma unroll
    for (int j = 0; j < 8; j++) xi[j] = xp[lane + 32 * j];
    float dq = g_deqx[t];
    float vals[NEXP];
    #pragma unroll
    for (int e = 0; e < NEXP; e++) {
        const int* wrp = (const int*)(g_wqr + e * DIMX);
        const int* wnp = (const int*)(g_wqn + e * DIMX);
        int ar = 0, an = 0;
        #pragma unroll
        for (int j = 0; j < 8; j++) {
            ar = __dp4a(xi[j], wrp[lane + 32 * j], ar);
            an = __dp4a(xi[j], wnp[lane + 32 * j], an);
        }
        #pragma unroll
        for (int o = 16; o; o >>= 1) {
            ar += __shfl_xor_sync(0xffffffffu, ar, o);
            an += __shfl_xor_sync(0xffffffffu, an, o);
        }
        if (lane == 0) {
            float lg = (float)ar * dq * g_mval[0];
            float nl = (float)an * dq * g_mval[1];
            float sp = fmaxf(nl, 0.f) + log1pf(expf(-fabsf(nl)));
            vals[e] = lg + eps[t * NEXP + e] * sp;
        }
    }
    if (lane == 0) {
        float v0 = -1e30f, v1 = -1e30f;
        int i0 = 0, i1 = 0;
        #pragma unroll
        for (int e = 0; e < NEXP; e++) {
            float v = vals[e];
            if (v > v0) { v1 = v0; i1 = i0; v0 = v; i0 = e; }
            else if (v > v1) { v1 = v; i1 = e; }
        }
        float ex = expf(v1 - v0);
        float inv = 1.0f / (1.0f + ex);
        int p0 = atomicAdd(&g_cnt[i0], 1);
        g_tok[i0 * TTOK + p0] = t;
        int p1 = atomicAdd(&g_cnt[i1], 1);
        g_tok[i1 * TTOK + p1] = t;
        g_tpe[t * 2]     = (i0 << 16) | p0;
        g_tpe[t * 2 + 1] = (i1 << 16) | p1;
        g_tg[t * 2]      = inv;
        g_tg[t * 2 + 1]  = ex * inv;
    }
}

__global__ void zero_cnt() { if (threadIdx.x < NEXP) g_cnt[threadIdx.x] = 0; }

__global__ void scan_off() {
    if (threadIdx.x == 0) {
        int o = 0;
        for (int e = 0; e < NEXP; e++) { g_off[e] = o; o += g_cnt[e]; }
    }
}

// ---------------- hidden quant ----------------
__global__ void h_quant() {
    int e = blockIdx.y, pos = blockIdx.x;
    if (pos >= g_cnt[e]) return;
    size_t row = (size_t)g_off[e] + pos;
    const float4* hp = (const float4*)(g_h + row * HIDX);
    int tid = threadIdx.x;
    float4 r[4];
    float ss = 0.f, am = 0.f;
    #pragma unroll
    for (int j = 0; j < 4; j++) {
        r[j] = hp[tid + 256 * j];
        ss += r[j].x * r[j].x + r[j].y * r[j].y + r[j].z * r[j].z + r[j].w * r[j].w;
        am = fmaxf(am, fmaxf(fmaxf(fabsf(r[j].x), fabsf(r[j].y)), fmaxf(fabsf(r[j].z), fabsf(r[j].w))));
    }
    __shared__ float shs[8], shm[8];
    #pragma unroll
    for (int o = 16; o; o >>= 1) {
        ss += __shfl_xor_sync(0xffffffffu, ss, o);
        am = fmaxf(am, __shfl_xor_sync(0xffffffffu, am, o));
    }
    if ((tid & 31) == 0) { shs[tid >> 5] = ss; shm[tid >> 5] = am; }
    __syncthreads();
    float tss = 0.f, tam = 0.f;
    #pragma unroll
    for (int j = 0; j < 8; j++) { tss += shs[j]; tam = fmaxf(tam, shm[j]); }
    float rs = rsqrtf(tss / (float)HIDX + 1e-6f);
    float a = fmaxf(tam * rs, 1e-5f);
    float sc = 127.0f / a;
    if (tid == 0) g_deqh[row] = a / 127.0f;
    char4* dst = (char4*)(g_hq + row * HIDX);
    #pragma unroll
    for (int j = 0; j < 4; j++) {
        char4 c;
        c.x = qi8(r[j].x * rs * sc); c.y = qi8(r[j].y * rs * sc);
        c.z = qi8(r[j].z * rs * sc); c.w = qi8(r[j].w * rs * sc);
        dst[tid + 256 * j] = c;
    }
}

// ---------------- pipelined int8 tensor-core grouped GEMM ----------------
#define BM 128
#define BN 128
#define BKK 64
#define LDSS 80   // 64 + 16 pad: conflict-free fragment reads

__device__ __forceinline__ void mma8(int (&c)[4], const unsigned (&a)[4], const unsigned (&b)[2]) {
    asm volatile(
        "mma.sync.aligned.m16n8k32.row.col.s32.s8.s8.s32 "
        "{%0,%1,%2,%3}, {%4,%5,%6,%7}, {%8,%9}, {%0,%1,%2,%3};\n"
        : "+r"(c[0]), "+r"(c[1]), "+r"(c[2]), "+r"(c[3])
        : "r"(a[0]), "r"(a[1]), "r"(a[2]), "r"(a[3]), "r"(b[0]), "r"(b[1]));
}

template <int MODE>
__global__ __launch_bounds__(256) void bit_gemm() {
    constexpr int K = (MODE == 1) ? DIMX : HIDX;
    constexpr int N = (MODE == 1) ? HIDX : DIMX;
    constexpr int NITER = K / BKK;
    const int e = blockIdx.z;
    const int cnt = g_cnt[e];
    const int m0 = blockIdx.y * BM;
    if (m0 >= cnt) return;
    const int n0 = blockIdx.x * BN;
    const int off = g_off[e];

    __shared__ signed char sA[2][BM * LDSS];
    __shared__ signed char sB[2][BN * LDSS];

    const int tid = threadIdx.x;
    const int lane = tid & 31, warp = tid >> 5;
    const int wm = warp >> 2, wn = warp & 3;   // 2x4 warp grid

    int acc[4][4][4];
    #pragma unroll
    for (int a = 0; a < 4; a++)
        #pragma unroll
        for (int b = 0; b < 4; b++)
            #pragma unroll
            for (int c = 0; c < 4; c++) acc[a][b][c] = 0;

    const int lr = tid >> 1;            // row this thread stages (0..127)
    const int lcb = (tid & 1) * 32;     // byte offset within 64B k-chunk
    const bool aok = (m0 + lr) < cnt;
    const signed char* Ap;
    if (MODE == 1) {
        int tok = aok ? g_tok[e * TTOK + m0 + lr] : 0;
        Ap = g_xq + (size_t)tok * K + lcb;
    } else {
        int r = aok ? (off + m0 + lr) : 0;
        Ap = g_hq + (size_t)r * K + lcb;
    }
    const unsigned aSz = aok ? 16u : 0u;
    const signed char* wsrc = (MODE == 1) ? g_wq1 : g_wq2;
    const signed char* Bp = wsrc + (size_t)e * N * K + (size_t)(n0 + lr) * K + lcb;

    uint32_t saw[2], sbw[2];
    #pragma unroll
    for (int s = 0; s < 2; s++) {
        saw[s] = s2u(&sA[s][lr * LDSS + lcb]);
        sbw[s] = s2u(&sB[s][lr * LDSS + lcb]);
    }

    auto load_stage = [&](int kb, int s) {
        asm volatile("cp.async.cg.shared.global [%0], [%1], 16, %2;"
                     :: "r"(saw[s]), "l"(Ap + kb), "r"(aSz) : "memory");
        asm volatile("cp.async.cg.shared.global [%0], [%1], 16, %2;"
                     :: "r"(saw[s] + 16), "l"(Ap + kb + 16), "r"(aSz) : "memory");
        asm volatile("cp.async.cg.shared.global [%0], [%1], 16, 16;"
                     :: "r"(sbw[s]), "l"(Bp + kb) : "memory");
        asm volatile("cp.async.cg.shared.global [%0], [%1], 16, 16;"
                     :: "r"(sbw[s] + 16), "l"(Bp + kb + 16) : "memory");
        asm volatile("cp.async.commit_group;" ::: "memory");
    };

    load_stage(0, 0);
    #pragma unroll 1
    for (int i = 0; i < NITER; i++) {
        const int s = i & 1;
        if (i + 1 < NITER) {
            load_stage((i + 1) * BKK, s ^ 1);
            asm volatile("cp.async.wait_group 1;" ::: "memory");
        } else {
            asm volatile("cp.async.wait_group 0;" ::: "memory");
        }
        __syncthreads();

        #pragma unroll
        for (int ks = 0; ks < 2; ks++) {
            unsigned af[4][4];
            #pragma unroll
            for (int mi = 0; mi < 4; mi++) {
                const signed char* p = sA[s] + (wm * 64 + mi * 16 + (lane >> 2)) * LDSS + ks * 32 + (lane & 3) * 4;
                af[mi][0] = *(const unsigned*)p;
                af[mi][1] = *(const unsigned*)(p + 8 * LDSS);
                af[mi][2] = *(const unsigned*)(p + 16);
                af[mi][3] = *(const unsigned*)(p + 8 * LDSS + 16);
            }
            unsigned bf[4][2];
            #pragma unroll
            for (int ni = 0; ni < 4; ni++) {
                const signed char* p = sB[s] + (wn * 32 + ni * 8 + (lane >> 2)) * LDSS + ks * 32 + (lane & 3) * 4;
                bf[ni][0] = *(const unsigned*)p;
                bf[ni][1] = *(const unsigned*)(p + 16);
            }
            #pragma unroll
            for (int mi = 0; mi < 4; mi++)
                #pragma unroll
                for (int ni = 0; ni < 4; ni++) mma8(acc[mi][ni], af[mi], bf[ni]);
        }
        __syncthreads();
    }

    if (MODE == 1) {
        const float m1 = g_mval[2 + e];
        #pragma unroll
        for (int mi = 0; mi < 4; mi++) {
            #pragma unroll
            for (int half = 0; half < 2; half++) {
                int rrow = wm * 64 + mi * 16 + (lane >> 2) + half * 8;
                int pos = m0 + rrow;
                if (pos < cnt) {
                    float d = g_deqx[g_tok[e * TTOK + pos]] * m1;
                    float* hrow = g_h + (size_t)(off + pos) * HIDX + n0;
                    #pragma unroll
                    for (int ni = 0; ni < 4; ni++) {
                        int col = wn * 32 + ni * 8 + (lane & 3) * 2;
                        float2 v;
                        v.x = fmaxf(0.f, (float)acc[mi][ni][half * 2 + 0] * d);
                        v.y = fmaxf(0.f, (float)acc[mi][ni][half * 2 + 1] * d);
                        *(float2*)(hrow + col) = v;
                    }
                }
            }
        }
    } else {
        const float m2 = g_mval[10 + e];
        #pragma unroll
        for (int mi = 0; mi < 4; mi++) {
            #pragma unroll
            for (int half = 0; half < 2; half++) {
                int rrow = wm * 64 + mi * 16 + (lane >> 2) + half * 8;
                int pos = m0 + rrow;
                if (pos < cnt) {
                    float d = g_deqh[off + pos] * m2;
                    float* yrow = g_y + (size_t)(off + pos) * DIMX + n0;
                    #pragma unroll
                    for (int ni = 0; ni < 4; ni++) {
                        int col = wn * 32 + ni * 8 + (lane & 3) * 2;
                        float2 v;
                        v.x = (float)acc[mi][ni][half * 2 + 0] * d;
                        v.y = (float)acc[mi][ni][half * 2 + 1] * d;
                        *(float2*)(yrow + col) = v;
                    }
                }
            }
        }
    }
}

// ---------------- gated combine (deterministic, atomic-free) ----------------
__global__ void combine(float* __restrict__ out) {
    int t = blockIdx.x, i = threadIdx.x;
    int a0 = g_tpe[t * 2], a1 = g_tpe[t * 2 + 1];
    float gA = g_tg[t * 2], gB = g_tg[t * 2 + 1];
    size_t r0 = (size_t)(g_off[a0 >> 16] + (a0 & 0xFFFF)) * DIMX;
    size_t r1 = (size_t)(g_off[a1 >> 16] + (a1 & 0xFFFF)) * DIMX;
    float4 v0 = ((const float4*)(g_y + r0))[i];
    float4 v1 = ((const float4*)(g_y + r1))[i];
    float4 o;
    o.x = v0.x * gA + v1.x * gB;
    o.y = v0.y * gA + v1.y * gB;
    o.z = v0.z * gA + v1.z * gB;
    o.w = v0.w * gA + v1.w * gB;
    ((float4*)(out + (size_t)t * DIMX))[i] = o;
}

// ---------------- launch ----------------
extern "C" void kernel_launch(void* const* d_in, const int* in_sizes, int n_in,
                              void* d_out, int out_size) {
    const float* x   = (const float*)d_in[0];
    const float* eps = (const float*)d_in[1];
    const float* wr  = (const float*)d_in[2];
    const float* wn  = (const float*)d_in[3];
    const float* w1  = (const float*)d_in[4];
    const float* w2  = (const float*)d_in[5];
    float* out = (float*)d_out;

    zero_cnt<<<1, 32>>>();
    stats_partial<<<dim3(64, 18), 256>>>(wr, wn, w1, w2);
    stats_final<<<1, 32>>>();
    wquant_small<<<64, 256>>>(wr, wn);
    wquant_big<<<32768, 256>>>(w1, 1);
    wquant_big<<<32768, 256>>>(w2, 2);
    act_quant<<<TTOK, 256>>>(x);
    router_kernel<<<TTOK / 8, 256>>>(eps);
    scan_off<<<1, 32>>>();
    bit_gemm<1><<<dim3(HIDX / BN, TTOK / BM, NEXP), 256>>>();
    h_quant<<<dim3(TTOK, NEXP), 256>>>();
    bit_gemm<2><<<dim3(DIMX / BN, TTOK / BM, NEXP), 256>>>();
    combine<<<TTOK, 256>>>(out);
}

// round 7
// speedup vs baseline: 1.1666x; 1.0267x over previous
#include <cuda_runtime.h>
#include <cstdint>

#define DIMX 1024
#define NEXP 8
#define HIDX 4096
#define TTOK 4096   // B*S = 2*2048

// ---------------- static scratch (no allocations allowed) ----------------
__device__ signed char g_wq1[(size_t)NEXP * HIDX * DIMX];   // ternary w1
__device__ signed char g_wq2[(size_t)NEXP * DIMX * HIDX];   // ternary w2
__device__ signed char g_wqr[NEXP * DIMX];
__device__ signed char g_wqn[NEXP * DIMX];
__device__ float g_partial[18 * 64];
__device__ float g_mval[18];
__device__ signed char g_xq[(size_t)TTOK * DIMX];
__device__ float g_deqx[TTOK];
__device__ int   g_cnt[NEXP];
__device__ int   g_tok[NEXP * TTOK];
__device__ int   g_tpe[TTOK * 2];    // (expert<<16)|pos per token slot
__device__ float g_tg[TTOK * 2];     // gates per token slot
__device__ float g_h[(size_t)2 * TTOK * HIDX];               // fp32 hidden
__device__ signed char g_hq[(size_t)2 * TTOK * HIDX];        // int8 hidden
__device__ float g_deqh[2 * TTOK];
__device__ float g_y[(size_t)2 * TTOK * DIMX];               // ungated expert outputs

// ---------------- helpers ----------------
__device__ __forceinline__ signed char terq(float x) {
    float r = rintf(x);
    r = fminf(1.f, fmaxf(-1.f, r));
    return (signed char)(int)r;
}
__device__ __forceinline__ signed char qi8(float x) {
    float r = rintf(x);
    r = fminf(127.f, fmaxf(-128.f, r));
    return (signed char)(int)r;
}
__device__ __forceinline__ uint32_t s2u(const void* p) {
    uint32_t a;
    asm("{ .reg .u64 t; cvta.to.shared.u64 t, %1; cvt.u32.u64 %0, t; }" : "=r"(a) : "l"(p));
    return a;
}
__device__ __forceinline__ void ldsm4(unsigned& r0, unsigned& r1, unsigned& r2, unsigned& r3,
                                      uint32_t a) {
    asm volatile("ldmatrix.sync.aligned.m8n8.x4.shared.b16 {%0,%1,%2,%3}, [%4];"
                 : "=r"(r0), "=r"(r1), "=r"(r2), "=r"(r3) : "r"(a));
}

// ---------------- 1) weight stats: per-tensor sum |w| ----------------
__global__ void stats_partial(const float* __restrict__ wr, const float* __restrict__ wn,
                              const float* __restrict__ w1, const float* __restrict__ w2) {
    int slot = blockIdx.y, chunk = blockIdx.x;
    const float4* p;
    int nvec;
    if (slot < 2) {
        if (chunk != 0) return;
        p = (const float4*)(slot ? wn : wr);
        nvec = NEXP * DIMX / 4;
    } else if (slot < 10) {
        p = (const float4*)(w1 + (size_t)(slot - 2) * HIDX * DIMX) + (size_t)chunk * 16384;
        nvec = 16384;
    } else {
        p = (const float4*)(w2 + (size_t)(slot - 10) * DIMX * HIDX) + (size_t)chunk * 16384;
        nvec = 16384;
    }
    float s = 0.f;
    for (int i = threadIdx.x; i < nvec; i += 256) {
        float4 v = p[i];
        s += fabsf(v.x) + fabsf(v.y) + fabsf(v.z) + fabsf(v.w);
    }
    __shared__ float sh[8];
    #pragma unroll
    for (int o = 16; o; o >>= 1) s += __shfl_xor_sync(0xffffffffu, s, o);
    if ((threadIdx.x & 31) == 0) sh[threadIdx.x >> 5] = s;
    __syncthreads();
    if (threadIdx.x == 0) {
        float t = 0.f;
        #pragma unroll
        for (int j = 0; j < 8; j++) t += sh[j];
        g_partial[slot * 64 + chunk] = t;
    }
}

// ---------------- 2) finalize: mvals + small-weight ternarize + zero counts ----------------
__global__ void finalize(const float* __restrict__ wr, const float* __restrict__ wn) {
    int tid = threadIdx.x;
    __shared__ float sm[18];
    if (tid < 18) {
        int nc = (tid < 2) ? 1 : 64;
        float sum = 0.f;
        for (int c = 0; c < nc; c++) sum += g_partial[tid * 64 + c];
        float nelem = (tid < 2) ? (float)(NEXP * DIMX) : (float)((size_t)HIDX * DIMX);
        float m = fmaxf(sum / nelem, 1e-5f);
        g_mval[tid] = m;
        sm[tid] = m;
    }
    if (tid < NEXP) g_cnt[tid] = 0;
    __syncthreads();
    float sc0 = 1.0f / sm[0], sc1 = 1.0f / sm[1];
    for (int i = tid; i < NEXP * DIMX; i += 256) {
        g_wqr[i] = terq(wr[i] * sc0);
        g_wqn[i] = terq(wn[i] * sc1);
    }
}

// ---------------- 3) mega: big-weight ternarize (z=0,1) + act-quant+router (z=2) ----------------
__global__ __launch_bounds__(256) void mega(const float* __restrict__ w1,
                                            const float* __restrict__ w2,
                                            const float* __restrict__ x,
                                            const float* __restrict__ eps) {
    int z = blockIdx.z;
    int tid = threadIdx.x;
    if (z < 2) {
        size_t i = (size_t)blockIdx.x * 256 + tid;   // float4 index, exactly covers grid
        int e = (int)(i >> 20);
        float sc = 1.0f / g_mval[(z == 0 ? 2 : 10) + e];
        float4 v = ((const float4*)(z == 0 ? w1 : w2))[i];
        char4 c;
        c.x = terq(v.x * sc); c.y = terq(v.y * sc); c.z = terq(v.z * sc); c.w = terq(v.w * sc);
        ((char4*)(z == 0 ? g_wq1 : g_wq2))[i] = c;
        return;
    }
    int t = blockIdx.x;
    if (t >= TTOK) return;

    __shared__ float shs[8], shm[8], svals[8], sdq[1];
    __shared__ int sx[256];

    float4 v = ((const float4*)(x + (size_t)t * DIMX))[tid];
    float ss = v.x * v.x + v.y * v.y + v.z * v.z + v.w * v.w;
    float am = fmaxf(fmaxf(fabsf(v.x), fabsf(v.y)), fmaxf(fabsf(v.z), fabsf(v.w)));
    #pragma unroll
    for (int o = 16; o; o >>= 1) {
        ss += __shfl_xor_sync(0xffffffffu, ss, o);
        am = fmaxf(am, __shfl_xor_sync(0xffffffffu, am, o));
    }
    if ((tid & 31) == 0) { shs[tid >> 5] = ss; shm[tid >> 5] = am; }
    __syncthreads();
    float tss = 0.f, tam = 0.f;
    #pragma unroll
    for (int j = 0; j < 8; j++) { tss += shs[j]; tam = fmaxf(tam, shm[j]); }
    float rs = rsqrtf(tss / (float)DIMX + 1e-6f);
    float a = fmaxf(tam * rs, 1e-5f);
    float sc = 127.0f / a;
    if (tid == 0) { g_deqx[t] = a / 127.0f; sdq[0] = a / 127.0f; }
    char4 c;
    c.x = qi8(v.x * rs * sc); c.y = qi8(v.y * rs * sc);
    c.z = qi8(v.z * rs * sc); c.w = qi8(v.w * rs * sc);
    ((char4*)(g_xq + (size_t)t * DIMX))[tid] = c;
    int ci;
    memcpy(&ci, &c, 4);
    sx[tid] = ci;
    __syncthreads();

    // router: warp w handles expert w
    int w = tid >> 5, lane = tid & 31;
    const int* wrp = (const int*)(g_wqr + w * DIMX);
    const int* wnp = (const int*)(g_wqn + w * DIMX);
    int ar = 0, an = 0;
    #pragma unroll
    for (int j = 0; j < 8; j++) {
        int xi = sx[lane + 32 * j];
        ar = __dp4a(xi, wrp[lane + 32 * j], ar);
        an = __dp4a(xi, wnp[lane + 32 * j], an);
    }
    #pragma unroll
    for (int o = 16; o; o >>= 1) {
        ar += __shfl_xor_sync(0xffffffffu, ar, o);
        an += __shfl_xor_sync(0xffffffffu, an, o);
    }
    if (lane == 0) {
        float dq = sdq[0];
        float lg = (float)ar * dq * g_mval[0];
        float nl = (float)an * dq * g_mval[1];
        float sp = fmaxf(nl, 0.f) + log1pf(expf(-fabsf(nl)));
        svals[w] = lg + eps[t * NEXP + w] * sp;
    }
    __syncthreads();
    if (tid == 0) {
        float v0 = -1e30f, v1 = -1e30f;
        int i0 = 0, i1 = 0;
        #pragma unroll
        for (int e = 0; e < NEXP; e++) {
            float vv = svals[e];
            if (vv > v0) { v1 = v0; i1 = i0; v0 = vv; i0 = e; }
            else if (vv > v1) { v1 = vv; i1 = e; }
        }
        float ex = expf(v1 - v0);
        float inv = 1.0f / (1.0f + ex);
        int p0 = atomicAdd(&g_cnt[i0], 1);
        g_tok[i0 * TTOK + p0] = t;
        int p1 = atomicAdd(&g_cnt[i1], 1);
        g_tok[i1 * TTOK + p1] = t;
        g_tpe[t * 2]     = (i0 << 16) | p0;
        g_tpe[t * 2 + 1] = (i1 << 16) | p1;
        g_tg[t * 2]      = inv;
        g_tg[t * 2 + 1]  = ex * inv;
    }
}

// ---------------- 4/6) pipelined int8 tensor-core grouped GEMM ----------------
#define BM 128
#define BN 128
#define BKK 64
#define LDSS 80          // 64 + 16 pad: conflict-free ldmatrix phases
#define STG_STRIDE (2 * BM * LDSS)   // A stage + B stage = 20480
#define GSMEM (4 * STG_STRIDE)       // 4 stages = 81920 B

__device__ __forceinline__ void mma8(int (&c)[4], const unsigned (&a)[4], const unsigned (&b)[2]) {
    asm volatile(
        "mma.sync.aligned.m16n8k32.row.col.s32.s8.s8.s32 "
        "{%0,%1,%2,%3}, {%4,%5,%6,%7}, {%8,%9}, {%0,%1,%2,%3};\n"
        : "+r"(c[0]), "+r"(c[1]), "+r"(c[2]), "+r"(c[3])
        : "r"(a[0]), "r"(a[1]), "r"(a[2]), "r"(a[3]), "r"(b[0]), "r"(b[1]));
}

template <int MODE>
__global__ __launch_bounds__(256) void bit_gemm() {
    constexpr int K = (MODE == 1) ? DIMX : HIDX;
    constexpr int N = (MODE == 1) ? HIDX : DIMX;
    constexpr int NITER = K / BKK;
    const int e = blockIdx.z;
    const int cnt = g_cnt[e];
    const int m0 = blockIdx.y * BM;
    if (m0 >= cnt) return;
    const int n0 = blockIdx.x * BN;
    int off = 0;
    #pragma unroll
    for (int j = 0; j < NEXP; j++) if (j < e) off += g_cnt[j];

    extern __shared__ char dsm[];
    const uint32_t smb = s2u(dsm);

    const int tid = threadIdx.x;
    const int lane = tid & 31, warp = tid >> 5;
    const int wm = warp >> 2, wn = warp & 3;   // 2x4 warp grid, warp tile 64x32

    int acc[4][4][4];
    #pragma unroll
    for (int a = 0; a < 4; a++)
        #pragma unroll
        for (int b = 0; b < 4; b++)
            #pragma unroll
            for (int c = 0; c < 4; c++) acc[a][b][c] = 0;

    const int lr = tid >> 1;            // staged row
    const int lcb = (tid & 1) * 32;     // byte offset within 64B k-chunk
    const bool aok = (m0 + lr) < cnt;
    const signed char* Ap;
    if (MODE == 1) {
        int tok = aok ? g_tok[e * TTOK + m0 + lr] : 0;
        Ap = g_xq + (size_t)tok * K + lcb;
    } else {
        int r = aok ? (off + m0 + lr) : 0;
        Ap = g_hq + (size_t)r * K + lcb;
    }
    const unsigned aSz = aok ? 16u : 0u;
    const signed char* wsrc = (MODE == 1) ? g_wq1 : g_wq2;
    const signed char* Bp = wsrc + (size_t)e * N * K + (size_t)(n0 + lr) * K + lcb;

    const uint32_t cpOff = (uint32_t)(lr * LDSS + lcb);
    // ldmatrix lane offsets (A: x4 = 16 rows x 2 k-halves; B: x4 = 2 n-groups x 2 k-halves)
    const uint32_t aLO = (uint32_t)((lane & 15) * LDSS + (lane >> 4) * 16);
    const uint32_t bLO = (uint32_t)(((lane >> 4) * 8 + (lane & 7)) * LDSS + ((lane >> 3) & 1) * 16);

    auto prefetch = [&](int it) {
        int s = it & 3;
        uint32_t ab = smb + s * STG_STRIDE + cpOff;
        uint32_t bb = ab + BM * LDSS;
        const signed char* as = Ap;
        const signed char* bs = Bp;
        unsigned asz = 0, bsz = 0;
        if (it < NITER) {
            as = Ap + it * BKK;
            bs = Bp + it * BKK;
            asz = aSz;
            bsz = 16;
        }
        asm volatile("cp.async.cg.shared.global [%0], [%1], 16, %2;" :: "r"(ab), "l"(as), "r"(asz) : "memory");
        asm volatile("cp.async.cg.shared.global [%0], [%1], 16, %2;" :: "r"(ab + 16), "l"(as + 16), "r"(asz) : "memory");
        asm volatile("cp.async.cg.shared.global [%0], [%1], 16, %2;" :: "r"(bb), "l"(bs), "r"(bsz) : "memory");
        asm volatile("cp.async.cg.shared.global [%0], [%1], 16, %2;" :: "r"(bb + 16), "l"(bs + 16), "r"(bsz) : "memory");
        asm volatile("cp.async.commit_group;" ::: "memory");
    };

    prefetch(0);
    prefetch(1);
    prefetch(2);
    #pragma unroll 1
    for (int i = 0; i < NITER; i++) {
        prefetch(i + 3);
        asm volatile("cp.async.wait_group 3;" ::: "memory");
        __syncthreads();
        const int s = i & 3;
        const uint32_t aB = smb + s * STG_STRIDE;
        const uint32_t bB = aB + BM * LDSS;
        #pragma unroll
        for (int ks = 0; ks < 2; ks++) {
            unsigned af[4][4];
            #pragma unroll
            for (int mi = 0; mi < 4; mi++)
                ldsm4(af[mi][0], af[mi][1], af[mi][2], af[mi][3],
                      aB + (uint32_t)((wm * 64 + mi * 16) * LDSS + ks * 32) + aLO);
            unsigned bf[4][2];
            #pragma unroll
            for (int np = 0; np < 2; np++)
                ldsm4(bf[np * 2][0], bf[np * 2][1], bf[np * 2 + 1][0], bf[np * 2 + 1][1],
                      bB + (uint32_t)((wn * 32 + np * 16) * LDSS + ks * 32) + bLO);
            #pragma unroll
            for (int mi = 0; mi < 4; mi++)
                #pragma unroll
                for (int ni = 0; ni < 4; ni++) mma8(acc[mi][ni], af[mi], bf[ni]);
        }
        __syncthreads();
    }

    if (MODE == 1) {
        const float m1 = g_mval[2 + e];
        #pragma unroll
        for (int mi = 0; mi < 4; mi++) {
            #pragma unroll
            for (int half = 0; half < 2; half++) {
                int rrow = wm * 64 + mi * 16 + (lane >> 2) + half * 8;
                int pos = m0 + rrow;
                if (pos < cnt) {
                    float d = g_deqx[g_tok[e * TTOK + pos]] * m1;
                    float* hrow = g_h + (size_t)(off + pos) * HIDX + n0;
                    #pragma unroll
                    for (int ni = 0; ni < 4; ni++) {
                        int col = wn * 32 + ni * 8 + (lane & 3) * 2;
                        float2 v;
                        v.x = fmaxf(0.f, (float)acc[mi][ni][half * 2 + 0] * d);
                        v.y = fmaxf(0.f, (float)acc[mi][ni][half * 2 + 1] * d);
                        *(float2*)(hrow + col) = v;
                    }
                }
            }
        }
    } else {
        const float m2 = g_mval[10 + e];
        #pragma unroll
        for (int mi = 0; mi < 4; mi++) {
            #pragma unroll
            for (int half = 0; half < 2; half++) {
                int rrow = wm * 64 + mi * 16 + (lane >> 2) + half * 8;
                int pos = m0 + rrow;
                if (pos < cnt) {
                    float d = g_deqh[off + pos] * m2;
                    float* yrow = g_y + (size_t)(off + pos) * DIMX + n0;
                    #pragma unroll
                    for (int ni = 0; ni < 4; ni++) {
                        int col = wn * 32 + ni * 8 + (lane & 3) * 2;
                        float2 v;
                        v.x = (float)acc[mi][ni][half * 2 + 0] * d;
                        v.y = (float)acc[mi][ni][half * 2 + 1] * d;
                        *(float2*)(yrow + col) = v;
                    }
                }
            }
        }
    }
}

// ---------------- 5) hidden quant: one block per packed row ----------------
__global__ void h_quant() {
    size_t row = blockIdx.x;   // 0 .. 2*TTOK-1 (all slots always filled)
    const float4* hp = (const float4*)(g_h + row * HIDX);
    int tid = threadIdx.x;
    float4 r[4];
    float ss = 0.f, am = 0.f;
    #pragma unroll
    for (int j = 0; j < 4; j++) {
        r[j] = hp[tid + 256 * j];
        ss += r[j].x * r[j].x + r[j].y * r[j].y + r[j].z * r[j].z + r[j].w * r[j].w;
        am = fmaxf(am, fmaxf(fmaxf(fabsf(r[j].x), fabsf(r[j].y)), fmaxf(fabsf(r[j].z), fabsf(r[j].w))));
    }
    __shared__ float shs[8], shm[8];
    #pragma unroll
    for (int o = 16; o; o >>= 1) {
        ss += __shfl_xor_sync(0xffffffffu, ss, o);
        am = fmaxf(am, __shfl_xor_sync(0xffffffffu, am, o));
    }
    if ((tid & 31) == 0) { shs[tid >> 5] = ss; shm[tid >> 5] = am; }
    __syncthreads();
    float tss = 0.f, tam = 0.f;
    #pragma unroll
    for (int j = 0; j < 8; j++) { tss += shs[j]; tam = fmaxf(tam, shm[j]); }
    float rs = rsqrtf(tss / (float)HIDX + 1e-6f);
    float a = fmaxf(tam * rs, 1e-5f);
    float sc = 127.0f / a;
    if (tid == 0) g_deqh[row] = a / 127.0f;
    char4* dst = (char4*)(g_hq + row * HIDX);
    #pragma unroll
    for (int j = 0; j < 4; j++) {
        char4 c;
        c.x = qi8(r[j].x * rs * sc); c.y = qi8(r[j].y * rs * sc);
        c.z = qi8(r[j].z * rs * sc); c.w = qi8(r[j].w * rs * sc);
        dst[tid + 256 * j] = c;
    }
}

// ---------------- 7) gated combine (deterministic, atomic-free) ----------------
__global__ void combine(float* __restrict__ out) {
    __shared__ int soff[NEXP];
    int t = blockIdx.x, i = threadIdx.x;
    if (i == 0) {
        int o = 0;
        #pragma unroll
        for (int j = 0; j < NEXP; j++) { soff[j] = o; o += g_cnt[j]; }
    }
    __syncthreads();
    int a0 = g_tpe[t * 2], a1 = g_tpe[t * 2 + 1];
    float gA = g_tg[t * 2], gB = g_tg[t * 2 + 1];
    size_t r0 = (size_t)(soff[a0 >> 16] + (a0 & 0xFFFF)) * DIMX;
    size_t r1 = (size_t)(soff[a1 >> 16] + (a1 & 0xFFFF)) * DIMX;
    float4 v0 = ((const float4*)(g_y + r0))[i];
    float4 v1 = ((const float4*)(g_y + r1))[i];
    float4 o;
    o.x = v0.x * gA + v1.x * gB;
    o.y = v0.y * gA + v1.y * gB;
    o.z = v0.z * gA + v1.z * gB;
    o.w = v0.w * gA + v1.w * gB;
    ((float4*)(out + (size_t)t * DIMX))[i] = o;
}

// ---------------- launch ----------------
extern "C" void kernel_launch(void* const* d_in, const int* in_sizes, int n_in,
                              void* d_out, int out_size) {
    const float* x   = (const float*)d_in[0];
    const float* eps = (const float*)d_in[1];
    const float* wr  = (const float*)d_in[2];
    const float* wn  = (const float*)d_in[3];
    const float* w1  = (const float*)d_in[4];
    const float* w2  = (const float*)d_in[5];
    float* out = (float*)d_out;

    cudaFuncSetAttribute(bit_gemm<1>, cudaFuncAttributeMaxDynamicSharedMemorySize, GSMEM);
    cudaFuncSetAttribute(bit_gemm<2>, cudaFuncAttributeMaxDynamicSharedMemorySize, GSMEM);

    stats_partial<<<dim3(64, 18), 256>>>(wr, wn, w1, w2);       // 1
    finalize<<<1, 256>>>(wr, wn);                               // 2
    mega<<<dim3(32768, 1, 3), 256>>>(w1, w2, x, eps);           // 3
    bit_gemm<1><<<dim3(HIDX / BN, TTOK / BM, NEXP), 256, GSMEM>>>();   // 4 <- profiled
    h_quant<<<2 * TTOK, 256>>>();                               // 5
    bit_gemm<2><<<dim3(DIMX / BN, TTOK / BM, NEXP), 256, GSMEM>>>();   // 6
    combine<<<TTOK, 256>>>(out);                                // 7
}